// round 1
// baseline (speedup 1.0000x reference)
#include <cuda_runtime.h>

#define BB 2
#define SS 5
#define CC 256
#define HH 192
#define WW 192
#define KK 7
#define NH 28
#define NW 28
#define HID 16

// Scratch (no cudaMalloc allowed): g means [b,s,c,nh,nw] + logits [b,s,nh,nw]
__device__ float g_buf[BB * SS * CC * NH * NW];       // 8.03 MB
__device__ float logits_buf[BB * SS * NH * NW];       // 31.4 KB

// ---------------------------------------------------------------------------
// Kernel 1: 7x7 window means (with zero padding beyond H/W, divide by 49)
// grid (NH, CC, BB*SS), block 192
// ---------------------------------------------------------------------------
__global__ void k_means(const float* __restrict__ x) {
    const int nh = blockIdx.x;
    const int c  = blockIdx.y;
    const int bs = blockIdx.z;           // b*SS + s
    const int t  = threadIdx.x;          // 0..191 (column)

    __shared__ float colsum[WW];

    const float* xim = x + (size_t)(bs * CC + c) * HH * WW;
    const int h0 = nh * KK;

    float sum = 0.f;
    #pragma unroll
    for (int i = 0; i < KK; i++) {
        int h = h0 + i;
        if (h < HH) sum += xim[(size_t)h * WW + t];
    }
    colsum[t] = sum;
    __syncthreads();

    if (t < NW) {
        float ws = 0.f;
        const int w0 = t * KK;
        #pragma unroll
        for (int i = 0; i < KK; i++) {
            int w = w0 + i;
            if (w < WW) ws += colsum[w];
        }
        g_buf[((size_t)(bs * CC + c) * NH + nh) * NW + t] = ws * (1.0f / (KK * KK));
    }
}

// ---------------------------------------------------------------------------
// Kernel 2: tiny MLP over C -> logits[b,s,nh,nw]
// grid (NH, SS, BB), block 448 = NW*HID
// ---------------------------------------------------------------------------
__global__ void k_mlp(const float* __restrict__ w1, const float* __restrict__ b1,
                      const float* __restrict__ w2, const float* __restrict__ b2,
                      const float* __restrict__ stat) {
    const int nh = blockIdx.x;
    const int s  = blockIdx.y;
    const int b  = blockIdx.z;
    const int tid = threadIdx.x;

    __shared__ float sg[CC * NW];        // 28672 B : g tile [c][nw]
    __shared__ float sw1[HID * CC];      // 16384 B
    __shared__ float sh[NW * HID];       //  1792 B

    const size_t gbase = (size_t)(b * SS + s) * CC * NH * NW + (size_t)nh * NW;
    for (int i = tid; i < CC * NW; i += blockDim.x) {
        int c = i / NW, nw = i % NW;
        sg[i] = g_buf[gbase + (size_t)c * NH * NW + nw];
    }
    for (int i = tid; i < HID * CC; i += blockDim.x) sw1[i] = w1[i];
    __syncthreads();

    // thread = (j, nw)
    {
        const int nw = tid % NW;
        const int j  = tid / NW;
        float acc = b1[j];
        #pragma unroll 8
        for (int c = 0; c < CC; c++)
            acc = fmaf(sg[c * NW + nw], sw1[j * CC + c], acc);
        sh[nw * HID + j] = fmaxf(acc, 0.f);
    }
    __syncthreads();

    if (tid < NW) {
        float lg = b2[0] + stat[s];
        #pragma unroll
        for (int j = 0; j < HID; j++) lg = fmaf(sh[tid * HID + j], w2[j], lg);
        logits_buf[((size_t)(b * SS + s) * NH + nh) * NW + tid] = lg;
    }
}

// ---------------------------------------------------------------------------
// Kernel 3: softmax over S + weighted fuse + interleaved write
// out[b,c, kh*28+nh, kw*28+nw] = sum_s wt[s][nw] * xpad[b,s,c, nh*7+kh, nw*7+kw]
// grid (NH, CC, BB), block 192
// ---------------------------------------------------------------------------
__global__ void k_fuse(const float* __restrict__ x, float* __restrict__ out) {
    const int nh = blockIdx.x;
    const int c  = blockIdx.y;
    const int b  = blockIdx.z;
    const int t  = threadIdx.x;          // 0..191 (output column)

    __shared__ float sm[SS * KK * WW];   // 26880 B : input rows [s][kh][w]
    __shared__ float swt[SS][NW];        // softmax weights

    // Vectorized coalesced load of 5 slices x 7 rows (zeros beyond H)
    const int h0 = nh * KK;
    const float4* x4 = (const float4*)x;
    for (int i = t; i < SS * KK * (WW / 4); i += blockDim.x) {
        const int q  = i % (WW / 4);
        const int r  = i / (WW / 4);     // r = s*KK + kh
        const int kh = r % KK;
        const int s  = r / KK;
        const int h  = h0 + kh;
        float4 v = make_float4(0.f, 0.f, 0.f, 0.f);
        if (h < HH)
            v = x4[((size_t)((b * SS + s) * CC + c) * HH + h) * (WW / 4) + q];
        *(float4*)&sm[r * WW + q * 4] = v;
    }

    // Softmax over S for each of the 28 windows in this strip
    if (t < NW) {
        float lg[SS];
        float mx = -1e30f;
        #pragma unroll
        for (int s = 0; s < SS; s++) {
            lg[s] = logits_buf[((size_t)(b * SS + s) * NH + nh) * NW + t];
            mx = fmaxf(mx, lg[s]);
        }
        float sum = 0.f;
        #pragma unroll
        for (int s = 0; s < SS; s++) { lg[s] = expf(lg[s] - mx); sum += lg[s]; }
        const float inv = 1.f / sum;
        #pragma unroll
        for (int s = 0; s < SS; s++) swt[s][t] = lg[s] * inv;
    }
    __syncthreads();

    // Output column t: kw = t/28, nw = t%28, source col = nw*7 + kw
    const int kw   = t / NW;
    const int nw   = t % NW;
    const int wsrc = nw * KK + kw;
    const bool valid = (wsrc < WW);      // padded (zero) source columns

    float wts[SS];
    #pragma unroll
    for (int s = 0; s < SS; s++) wts[s] = swt[s][nw];

    float* obase = out + (size_t)(b * CC + c) * HH * WW;
    #pragma unroll
    for (int kh = 0; kh < KK; kh++) {
        const int y = kh * NH + nh;
        if (y < HH) {
            float v = 0.f;
            if (valid) {
                #pragma unroll
                for (int s = 0; s < SS; s++)
                    v = fmaf(wts[s], sm[(s * KK + kh) * WW + wsrc], v);
            }
            obase[(size_t)y * WW + t] = v;
        }
    }
}

// ---------------------------------------------------------------------------
extern "C" void kernel_launch(void* const* d_in, const int* in_sizes, int n_in,
                              void* d_out, int out_size) {
    const float* x    = (const float*)d_in[0];
    const float* w1   = (const float*)d_in[1];
    const float* b1   = (const float*)d_in[2];
    const float* w2   = (const float*)d_in[3];
    const float* b2   = (const float*)d_in[4];
    const float* stat = (const float*)d_in[5];
    float* out = (float*)d_out;

    k_means<<<dim3(NH, CC, BB * SS), WW>>>(x);
    k_mlp  <<<dim3(NH, SS, BB), NW * HID>>>(w1, b1, w2, b2, stat);
    k_fuse <<<dim3(NH, CC, BB), WW>>>(x, out);
}

// round 2
// speedup vs baseline: 1.2099x; 1.2099x over previous
#include <cuda_runtime.h>

#define BB 2
#define SS 5
#define CC 256
#define HH 192
#define WW 192
#define KK 7
#define NH 28
#define NW 28
#define HID 16

// Scratch (no cudaMalloc allowed): g means [b,s,c,nh,nw] + logits [b,s,nh,nw]
__device__ float g_buf[BB * SS * CC * NH * NW];       // 8.03 MB
__device__ float logits_buf[BB * SS * NH * NW];       // 31.4 KB

// ---------------------------------------------------------------------------
// Kernel 1: 7x7 window means, one block per (bs, c) image.
// Block = 336 threads = 7 rows x 48 float4-quads. Iterates over 28 strips
// with software pipelining: strip n+1's global loads issue before strip n's
// reduction barriers, so DRAM latency is hidden behind the smem phases.
// ---------------------------------------------------------------------------
__global__ __launch_bounds__(336) void k_means(const float* __restrict__ x) {
    const int c   = blockIdx.x;
    const int bs  = blockIdx.y;           // b*SS + s
    const int tid = threadIdx.x;          // 0..335
    const int q   = tid % 48;             // float4 quad within row
    const int kh  = tid / 48;             // 0..6 row within strip

    __shared__ float4 srow[KK][48];       // strip rows (5376 B)
    __shared__ float  scol[2][WW];        // double-buffered column sums

    const float4* xim4 = (const float4*)(x + (size_t)(bs * CC + c) * HH * WW);

    // prologue: load strip 0 (rows 0..6 always in-bounds)
    float4 v = xim4[kh * 48 + q];

    for (int nh = 0; nh < NH; ++nh) {
        // issue next strip's load early (overlaps with reduction below)
        float4 vn = make_float4(0.f, 0.f, 0.f, 0.f);
        const int hn = (nh + 1) * KK + kh;
        if (nh + 1 < NH && hn < HH) vn = xim4[hn * 48 + q];

        srow[kh][q] = v;
        __syncthreads();

        // phase A: sum 7 rows -> 192 column sums (48 threads, float4 each)
        if (tid < 48) {
            float4 a = srow[0][tid];
            #pragma unroll
            for (int r = 1; r < KK; r++) {
                float4 b = srow[r][tid];
                a.x += b.x; a.y += b.y; a.z += b.z; a.w += b.w;
            }
            *(float4*)&scol[nh & 1][tid * 4] = a;
        }
        __syncthreads();

        // phase B: 7-col window sums (28 threads). No 3rd barrier needed:
        // scol is double-buffered and srow rewrite is fenced by next barrier.
        if (tid < NW) {
            float ws = 0.f;
            const int w0 = tid * KK;
            #pragma unroll
            for (int i = 0; i < KK; i++) {
                const int w = w0 + i;
                if (w < WW) ws += scol[nh & 1][w];
            }
            g_buf[((size_t)(bs * CC + c) * NH + nh) * NW + tid] = ws * (1.0f / (KK * KK));
        }

        v = vn;
    }
}

// ---------------------------------------------------------------------------
// Kernel 2: tiny MLP over C -> logits[b,s,nh,nw]
// grid (NH, SS, BB), block 448 = NW*HID
// ---------------------------------------------------------------------------
__global__ void k_mlp(const float* __restrict__ w1, const float* __restrict__ b1,
                      const float* __restrict__ w2, const float* __restrict__ b2,
                      const float* __restrict__ stat) {
    const int nh = blockIdx.x;
    const int s  = blockIdx.y;
    const int b  = blockIdx.z;
    const int tid = threadIdx.x;

    __shared__ float sg[CC * NW];        // 28672 B : g tile [c][nw]
    __shared__ float sw1[HID * CC];      // 16384 B
    __shared__ float sh[NW * HID];       //  1792 B

    const size_t gbase = (size_t)(b * SS + s) * CC * NH * NW + (size_t)nh * NW;
    for (int i = tid; i < CC * NW; i += blockDim.x) {
        int c = i / NW, nw = i % NW;
        sg[i] = g_buf[gbase + (size_t)c * NH * NW + nw];
    }
    for (int i = tid; i < HID * CC; i += blockDim.x) sw1[i] = w1[i];
    __syncthreads();

    // thread = (j, nw)
    {
        const int nw = tid % NW;
        const int j  = tid / NW;
        float acc = b1[j];
        #pragma unroll 8
        for (int c = 0; c < CC; c++)
            acc = fmaf(sg[c * NW + nw], sw1[j * CC + c], acc);
        sh[nw * HID + j] = fmaxf(acc, 0.f);
    }
    __syncthreads();

    if (tid < NW) {
        float lg = b2[0] + stat[s];
        #pragma unroll
        for (int j = 0; j < HID; j++) lg = fmaf(sh[tid * HID + j], w2[j], lg);
        logits_buf[((size_t)(b * SS + s) * NH + nh) * NW + tid] = lg;
    }
}

// ---------------------------------------------------------------------------
// Kernel 3: softmax over S + weighted fuse + interleaved write
// out[b,c, kh*28+nh, kw*28+nw] = sum_s wt[s][nw] * xpad[b,s,c, nh*7+kh, nw*7+kw]
// grid (NH, CC, BB), block 192
// ---------------------------------------------------------------------------
__global__ void k_fuse(const float* __restrict__ x, float* __restrict__ out) {
    const int nh = blockIdx.x;
    const int c  = blockIdx.y;
    const int b  = blockIdx.z;
    const int t  = threadIdx.x;          // 0..191 (output column)

    __shared__ float sm[SS * KK * WW];   // 26880 B : input rows [s][kh][w]
    __shared__ float swt[SS][NW];        // softmax weights

    // Vectorized coalesced load of 5 slices x 7 rows (zeros beyond H)
    const int h0 = nh * KK;
    const float4* x4 = (const float4*)x;
    for (int i = t; i < SS * KK * (WW / 4); i += blockDim.x) {
        const int q  = i % (WW / 4);
        const int r  = i / (WW / 4);     // r = s*KK + kh
        const int kh = r % KK;
        const int s  = r / KK;
        const int h  = h0 + kh;
        float4 v = make_float4(0.f, 0.f, 0.f, 0.f);
        if (h < HH)
            v = x4[((size_t)((b * SS + s) * CC + c) * HH + h) * (WW / 4) + q];
        *(float4*)&sm[r * WW + q * 4] = v;
    }

    // Softmax over S for each of the 28 windows in this strip
    if (t < NW) {
        float lg[SS];
        float mx = -1e30f;
        #pragma unroll
        for (int s = 0; s < SS; s++) {
            lg[s] = logits_buf[((size_t)(b * SS + s) * NH + nh) * NW + t];
            mx = fmaxf(mx, lg[s]);
        }
        float sum = 0.f;
        #pragma unroll
        for (int s = 0; s < SS; s++) { lg[s] = expf(lg[s] - mx); sum += lg[s]; }
        const float inv = 1.f / sum;
        #pragma unroll
        for (int s = 0; s < SS; s++) swt[s][t] = lg[s] * inv;
    }
    __syncthreads();

    // Output column t: kw = t/28, nw = t%28, source col = nw*7 + kw
    const int kw   = t / NW;
    const int nw   = t % NW;
    const int wsrc = nw * KK + kw;
    const bool valid = (wsrc < WW);      // padded (zero) source columns

    float wts[SS];
    #pragma unroll
    for (int s = 0; s < SS; s++) wts[s] = swt[s][nw];

    float* obase = out + (size_t)(b * CC + c) * HH * WW;
    #pragma unroll
    for (int kh = 0; kh < KK; kh++) {
        const int y = kh * NH + nh;
        if (y < HH) {
            float v = 0.f;
            if (valid) {
                #pragma unroll
                for (int s = 0; s < SS; s++)
                    v = fmaf(wts[s], sm[(s * KK + kh) * WW + wsrc], v);
            }
            obase[(size_t)y * WW + t] = v;
        }
    }
}

// ---------------------------------------------------------------------------
extern "C" void kernel_launch(void* const* d_in, const int* in_sizes, int n_in,
                              void* d_out, int out_size) {
    const float* x    = (const float*)d_in[0];
    const float* w1   = (const float*)d_in[1];
    const float* b1   = (const float*)d_in[2];
    const float* w2   = (const float*)d_in[3];
    const float* b2   = (const float*)d_in[4];
    const float* stat = (const float*)d_in[5];
    float* out = (float*)d_out;

    k_means<<<dim3(CC, BB * SS), 336>>>(x);
    k_mlp  <<<dim3(NH, SS, BB), NW * HID>>>(w1, b1, w2, b2, stat);
    k_fuse <<<dim3(NH, CC, BB), WW>>>(x, out);
}

// round 3
// speedup vs baseline: 1.4026x; 1.1593x over previous
#include <cuda_runtime.h>

#define BB 2
#define SS 5
#define CC 256
#define HH 192
#define WW 192
#define KK 7
#define NH 28
#define NW 28
#define HID 16

__device__ float g_buf[BB * SS * CC * NH * NW];       // 8.03 MB
__device__ float logits_buf[BB * SS * NH * NW];       // 31.4 KB

// ---------------------------------------------------------------------------
// Kernel 1: 7x7 window means. Block = 336 threads handles 4 independent
// strips of one (bs,c) image: 4 front-batched float4 loads per thread
// (MLP_p1=4), one barrier, then both reduction phases for all 4 strips.
// grid (CC, BB*SS, 7)
// ---------------------------------------------------------------------------
__global__ __launch_bounds__(336) void k_means(const float* __restrict__ x) {
    const int c   = blockIdx.x;
    const int bs  = blockIdx.y;           // b*SS + s
    const int z   = blockIdx.z;           // strip group: strips z*4 .. z*4+3
    const int tid = threadIdx.x;          // 0..335
    const int q   = tid % 48;             // float4 quad within row
    const int kh  = tid / 48;             // 0..6 row within strip

    __shared__ float4 srow[4][KK][48];    // 21504 B
    __shared__ float  scol[4][WW];        //  3072 B

    const float4* xim4 = (const float4*)(x + (size_t)(bs * CC + c) * HH * WW);

    // 4 independent loads, front-batched
    float4 v[4];
    #pragma unroll
    for (int g = 0; g < 4; g++) {
        const int h = (z * 4 + g) * KK + kh;
        if (h < HH) v[g] = xim4[h * 48 + q];
        else        v[g] = make_float4(0.f, 0.f, 0.f, 0.f);
    }
    #pragma unroll
    for (int g = 0; g < 4; g++) srow[g][kh][q] = v[g];
    __syncthreads();

    // phase A: per strip, sum 7 rows -> 192 column sums (192 threads)
    if (tid < 192) {
        const int g = tid / 48, qq = tid % 48;
        float4 a = srow[g][0][qq];
        #pragma unroll
        for (int r = 1; r < KK; r++) {
            float4 b = srow[g][r][qq];
            a.x += b.x; a.y += b.y; a.z += b.z; a.w += b.w;
        }
        *(float4*)&scol[g][qq * 4] = a;
    }
    __syncthreads();

    // phase B: 7-col window sums (112 threads)
    if (tid < 4 * NW) {
        const int g = tid / NW, nw = tid % NW;
        const int w0 = nw * KK;
        float ws = 0.f;
        #pragma unroll
        for (int i = 0; i < KK; i++) {
            const int w = w0 + i;
            if (w < WW) ws += scol[g][w];
        }
        g_buf[((size_t)(bs * CC + c) * NH + (z * 4 + g)) * NW + nw] = ws * (1.0f / (KK * KK));
    }
}

// ---------------------------------------------------------------------------
// Kernel 2: tiny MLP over C -> logits[b,s,nh,nw]
// grid (NH, SS, BB), block 448 = NW*HID
// ---------------------------------------------------------------------------
__global__ void k_mlp(const float* __restrict__ w1, const float* __restrict__ b1,
                      const float* __restrict__ w2, const float* __restrict__ b2,
                      const float* __restrict__ stat) {
    const int nh = blockIdx.x;
    const int s  = blockIdx.y;
    const int b  = blockIdx.z;
    const int tid = threadIdx.x;

    __shared__ float sg[CC * NW];
    __shared__ float sw1[HID * CC];
    __shared__ float sh[NW * HID];

    const size_t gbase = (size_t)(b * SS + s) * CC * NH * NW + (size_t)nh * NW;
    for (int i = tid; i < CC * NW; i += blockDim.x) {
        int c = i / NW, nw = i % NW;
        sg[i] = g_buf[gbase + (size_t)c * NH * NW + nw];
    }
    for (int i = tid; i < HID * CC; i += blockDim.x) sw1[i] = w1[i];
    __syncthreads();

    {
        const int nw = tid % NW;
        const int j  = tid / NW;
        float acc = b1[j];
        #pragma unroll 8
        for (int c = 0; c < CC; c++)
            acc = fmaf(sg[c * NW + nw], sw1[j * CC + c], acc);
        sh[nw * HID + j] = fmaxf(acc, 0.f);
    }
    __syncthreads();

    if (tid < NW) {
        float lg = b2[0] + stat[s];
        #pragma unroll
        for (int j = 0; j < HID; j++) lg = fmaf(sh[tid * HID + j], w2[j], lg);
        logits_buf[((size_t)(b * SS + s) * NH + nh) * NW + tid] = lg;
    }
}

// ---------------------------------------------------------------------------
// Kernel 3: softmax over S + weighted fuse, 2 channels per block.
// grid (NH, CC/2, BB), block 384, dynamic smem 54.3 KB
// ---------------------------------------------------------------------------
#define FUSE_SM (SS * KK * WW)           // 6720 floats per channel

__global__ __launch_bounds__(384) void k_fuse(const float* __restrict__ x,
                                              float* __restrict__ out) {
    const int nh = blockIdx.x;
    const int c0 = blockIdx.y * 2;
    const int b  = blockIdx.z;
    const int t  = threadIdx.x;          // 0..383

    extern __shared__ float smem[];
    float* sm  = smem;                   // [2][SS*KK*WW]
    float* swt = smem + 2 * FUSE_SM;     // [SS][NW]

    // Coalesced float4 load of 2 channels x 5 slices x 7 rows
    const int h0 = nh * KK;
    const float4* x4 = (const float4*)x;
    for (int i = t; i < 2 * SS * KK * (WW / 4); i += 384) {
        const int q  = i % (WW / 4);
        const int r  = i / (WW / 4);     // r = (ci*SS + s)*KK + kh
        const int kh = r % KK;
        const int sc = r / KK;           // ci*SS + s
        const int s  = sc % SS;
        const int ci = sc / SS;
        const int h  = h0 + kh;
        float4 v = make_float4(0.f, 0.f, 0.f, 0.f);
        if (h < HH)
            v = x4[((size_t)((b * SS + s) * CC + c0 + ci) * HH + h) * (WW / 4) + q];
        *(float4*)&sm[(ci * SS * KK + s * KK + kh) * WW + q * 4] = v;
    }

    // Softmax over S for the 28 windows in this strip (shared by both channels)
    if (t < NW) {
        float lg[SS];
        float mx = -1e30f;
        #pragma unroll
        for (int s = 0; s < SS; s++) {
            lg[s] = logits_buf[((size_t)(b * SS + s) * NH + nh) * NW + t];
            mx = fmaxf(mx, lg[s]);
        }
        float sum = 0.f;
        #pragma unroll
        for (int s = 0; s < SS; s++) { lg[s] = expf(lg[s] - mx); sum += lg[s]; }
        const float inv = 1.f / sum;
        #pragma unroll
        for (int s = 0; s < SS; s++) swt[s * NW + t] = lg[s] * inv;
    }
    __syncthreads();

    // thread -> (ci, output column)
    const int ci   = t / WW;             // 0..1
    const int col  = t % WW;             // 0..191
    const int kw   = col / NW;
    const int nw   = col % NW;
    const int wsrc = nw * KK + kw;
    const bool valid = (wsrc < WW);

    float wts[SS];
    #pragma unroll
    for (int s = 0; s < SS; s++) wts[s] = swt[s * NW + nw];

    const float* smc = sm + ci * SS * KK * WW;
    float* obase = out + (size_t)(b * CC + c0 + ci) * HH * WW;
    #pragma unroll
    for (int kh = 0; kh < KK; kh++) {
        const int y = kh * NH + nh;
        if (y < HH) {
            float v = 0.f;
            if (valid) {
                #pragma unroll
                for (int s = 0; s < SS; s++)
                    v = fmaf(wts[s], smc[(s * KK + kh) * WW + wsrc], v);
            }
            obase[(size_t)y * WW + col] = v;
        }
    }
}

// ---------------------------------------------------------------------------
extern "C" void kernel_launch(void* const* d_in, const int* in_sizes, int n_in,
                              void* d_out, int out_size) {
    const float* x    = (const float*)d_in[0];
    const float* w1   = (const float*)d_in[1];
    const float* b1   = (const float*)d_in[2];
    const float* w2   = (const float*)d_in[3];
    const float* b2   = (const float*)d_in[4];
    const float* stat = (const float*)d_in[5];
    float* out = (float*)d_out;

    const int fuse_smem = (2 * FUSE_SM + SS * NW) * sizeof(float);  // ~55.9 KB
    cudaFuncSetAttribute(k_fuse, cudaFuncAttributeMaxDynamicSharedMemorySize, fuse_smem);

    k_means<<<dim3(CC, BB * SS, 7), 336>>>(x);
    k_mlp  <<<dim3(NH, SS, BB), NW * HID>>>(w1, b1, w2, b2, stat);
    k_fuse <<<dim3(NH, CC / 2, BB), 384, fuse_smem>>>(x, out);
}

// round 4
// speedup vs baseline: 1.6556x; 1.1804x over previous
#include <cuda_runtime.h>

#define BB 2
#define SS 5
#define CC 256
#define HH 192
#define WW 192
#define KK 7
#define NH 28
#define NW 28
#define HID 16

__device__ float g_buf[BB * SS * CC * NH * NW];       // 8.03 MB
__device__ float logits_buf[BB * SS * NH * NW];       // 31.4 KB

// ---------------------------------------------------------------------------
// Kernel 1: 7x7 window means. Block = 336 threads handles 4 independent
// strips of one (bs,c) image: 4 front-batched float4 loads per thread,
// one barrier, then both reduction phases. grid (CC, BB*SS, 7)
// ---------------------------------------------------------------------------
__global__ __launch_bounds__(336) void k_means(const float* __restrict__ x) {
    const int c   = blockIdx.x;
    const int bs  = blockIdx.y;           // b*SS + s
    const int z   = blockIdx.z;           // strip group: strips z*4 .. z*4+3
    const int tid = threadIdx.x;
    const int q   = tid % 48;
    const int kh  = tid / 48;

    __shared__ float4 srow[4][KK][48];
    __shared__ float  scol[4][WW];

    const float4* xim4 = (const float4*)(x + (size_t)(bs * CC + c) * HH * WW);

    float4 v[4];
    #pragma unroll
    for (int g = 0; g < 4; g++) {
        const int h = (z * 4 + g) * KK + kh;
        if (h < HH) v[g] = xim4[h * 48 + q];
        else        v[g] = make_float4(0.f, 0.f, 0.f, 0.f);
    }
    #pragma unroll
    for (int g = 0; g < 4; g++) srow[g][kh][q] = v[g];
    __syncthreads();

    if (tid < 192) {
        const int g = tid / 48, qq = tid % 48;
        float4 a = srow[g][0][qq];
        #pragma unroll
        for (int r = 1; r < KK; r++) {
            float4 b = srow[g][r][qq];
            a.x += b.x; a.y += b.y; a.z += b.z; a.w += b.w;
        }
        *(float4*)&scol[g][qq * 4] = a;
    }
    __syncthreads();

    if (tid < 4 * NW) {
        const int g = tid / NW, nw = tid % NW;
        const int w0 = nw * KK;
        float ws = 0.f;
        #pragma unroll
        for (int i = 0; i < KK; i++) {
            const int w = w0 + i;
            if (w < WW) ws += scol[g][w];
        }
        g_buf[((size_t)(bs * CC + c) * NH + (z * 4 + g)) * NW + nw] = ws * (1.0f / (KK * KK));
    }
}

// ---------------------------------------------------------------------------
// Kernel 2: tiny MLP over C -> logits[b,s,nh,nw]
// grid (NH, SS, BB), block 448 = NW*HID
// ---------------------------------------------------------------------------
__global__ void k_mlp(const float* __restrict__ w1, const float* __restrict__ b1,
                      const float* __restrict__ w2, const float* __restrict__ b2,
                      const float* __restrict__ stat) {
    const int nh = blockIdx.x;
    const int s  = blockIdx.y;
    const int b  = blockIdx.z;
    const int tid = threadIdx.x;

    __shared__ float sg[CC * NW];
    __shared__ float sw1[HID * CC];
    __shared__ float sh[NW * HID];

    const size_t gbase = (size_t)(b * SS + s) * CC * NH * NW + (size_t)nh * NW;
    for (int i = tid; i < CC * NW; i += blockDim.x) {
        int c = i / NW, nw = i % NW;
        sg[i] = g_buf[gbase + (size_t)c * NH * NW + nw];
    }
    for (int i = tid; i < HID * CC; i += blockDim.x) sw1[i] = w1[i];
    __syncthreads();

    {
        const int nw = tid % NW;
        const int j  = tid / NW;
        float acc = b1[j];
        #pragma unroll 8
        for (int c = 0; c < CC; c++)
            acc = fmaf(sg[c * NW + nw], sw1[j * CC + c], acc);
        sh[nw * HID + j] = fmaxf(acc, 0.f);
    }
    __syncthreads();

    if (tid < NW) {
        float lg = b2[0] + stat[s];
        #pragma unroll
        for (int j = 0; j < HID; j++) lg = fmaf(sh[tid * HID + j], w2[j], lg);
        logits_buf[((size_t)(b * SS + s) * NH + nh) * NW + tid] = lg;
    }
}

// ---------------------------------------------------------------------------
// Kernel 3: softmax over S + weighted fuse, 2 channels per block.
// Block = 480 threads = 48 quads x 10 rows; each thread does EXACTLY 7
// unconditional, independent float4 loads covering all 70 rows
// (2ch x 5 slices x 7 rows) -> deep MLP, no loop divergence.
// grid (NH, CC/2, BB), dynamic smem ~53 KB -> 4 blocks/SM, 1920 thr/SM.
// ---------------------------------------------------------------------------
#define FUSE_SM (SS * KK * WW)           // 6720 floats per channel
#define FUSE_T  480

__global__ __launch_bounds__(FUSE_T) void k_fuse(const float* __restrict__ x,
                                                 float* __restrict__ out) {
    const int nh = blockIdx.x;
    const int c0 = blockIdx.y * 2;
    const int b  = blockIdx.z;
    const int t  = threadIdx.x;          // 0..479

    extern __shared__ float smem[];
    float* sm  = smem;                   // [2*SS*KK][WW], r = (ci*SS+s)*KK+kh
    float* swt = smem + 2 * FUSE_SM;     // [SS][NW]

    const int h0 = nh * KK;
    const float4* x4 = (const float4*)x;

    // 7 front-batched independent loads per thread (q fixed, row += 10)
    const int q  = t % 48;
    const int r0 = t / 48;               // 0..9
    float4 v[7];
    int rr[7];
    #pragma unroll
    for (int it = 0; it < KK; it++) {
        const int r  = r0 + it * 10;     // 0..69
        const int kh = r % KK;
        const int sc = r / KK;           // ci*SS + s
        const int s  = sc % SS;
        const int ci = sc / SS;
        const int h  = h0 + kh;
        rr[it] = r;
        if (h < HH)
            v[it] = x4[((size_t)((b * SS + s) * CC + c0 + ci) * HH + h) * 48 + q];
        else
            v[it] = make_float4(0.f, 0.f, 0.f, 0.f);
    }
    #pragma unroll
    for (int it = 0; it < KK; it++)
        *(float4*)&sm[rr[it] * WW + q * 4] = v[it];

    // Softmax over S (28 windows, shared by both channels)
    if (t < NW) {
        float lg[SS];
        float mx = -1e30f;
        #pragma unroll
        for (int s = 0; s < SS; s++) {
            lg[s] = logits_buf[((size_t)(b * SS + s) * NH + nh) * NW + t];
            mx = fmaxf(mx, lg[s]);
        }
        float sum = 0.f;
        #pragma unroll
        for (int s = 0; s < SS; s++) { lg[s] = expf(lg[s] - mx); sum += lg[s]; }
        const float inv = 1.f / sum;
        #pragma unroll
        for (int s = 0; s < SS; s++) swt[s * NW + t] = lg[s] * inv;
    }
    __syncthreads();

    // Compute + store: threads 0..383 -> (ci, output column)
    if (t < 2 * WW) {
        const int ci   = t / WW;
        const int col  = t % WW;
        const int kw   = col / NW;
        const int nw   = col % NW;
        const int wsrc = nw * KK + kw;
        const bool valid = (wsrc < WW);

        float wts[SS];
        #pragma unroll
        for (int s = 0; s < SS; s++) wts[s] = swt[s * NW + nw];

        const float* smc = sm + ci * SS * KK * WW;
        float* obase = out + (size_t)(b * CC + c0 + ci) * HH * WW;
        #pragma unroll
        for (int kh = 0; kh < KK; kh++) {
            const int y = kh * NH + nh;
            if (y < HH) {
                float vv = 0.f;
                if (valid) {
                    #pragma unroll
                    for (int s = 0; s < SS; s++)
                        vv = fmaf(wts[s], smc[(s * KK + kh) * WW + wsrc], vv);
                }
                obase[(size_t)y * WW + col] = vv;
            }
        }
    }
}

// ---------------------------------------------------------------------------
extern "C" void kernel_launch(void* const* d_in, const int* in_sizes, int n_in,
                              void* d_out, int out_size) {
    const float* x    = (const float*)d_in[0];
    const float* w1   = (const float*)d_in[1];
    const float* b1   = (const float*)d_in[2];
    const float* w2   = (const float*)d_in[3];
    const float* b2   = (const float*)d_in[4];
    const float* stat = (const float*)d_in[5];
    float* out = (float*)d_out;

    const int fuse_smem = (2 * FUSE_SM + SS * NW) * sizeof(float);  // ~53 KB
    cudaFuncSetAttribute(k_fuse, cudaFuncAttributeMaxDynamicSharedMemorySize, fuse_smem);

    k_means<<<dim3(CC, BB * SS, 7), 336>>>(x);
    k_mlp  <<<dim3(NH, SS, BB), NW * HID>>>(w1, b1, w2, b2, stat);
    k_fuse <<<dim3(NH, CC / 2, BB), FUSE_T, fuse_smem>>>(x, out);
}